// round 7
// baseline (speedup 1.0000x reference)
#include <cuda_runtime.h>
#include <cuda_bf16.h>

#define NN   100000
#define NPAD 100096
#define EMAX 1600000
#define D    64

#define SCAN_CHUNK  512
#define SCAN_BLOCKS ((NN + SCAN_CHUNK - 1) / SCAN_CHUNK)   // 196

#define ST_AGG (1u << 30)
#define ST_INC (2u << 30)
#define ST_VAL 0x00FFFFFFu

// ---------------- scratch (static device globals; no allocation) ----------------
__device__ float g_buf1[NPAD * D];
__device__ float g_buf2[NPAD * D];
__device__ float g_mean[NPAD * D];
__device__ int   g_csr[EMAX];
__device__ int   g_rowptr[NN + 1];
__device__ int   g_cnt[NN];        // zero-initialized; k_scanapply re-zeroes after use
__device__ int   g_cursor[NN];
__device__ float g_rdeg[NN];
__device__ unsigned g_scanstate[SCAN_BLOCKS];  // zeroed by k_deg each call

// ---------------- helpers ----------------
// int64 edge_index (little-endian, values < 2^31) has all-zero odd 32-bit words.
__device__ __forceinline__ int block_is64(const int* __restrict__ ei32) {
    __shared__ int sh;
    if (threadIdx.x < 32) {
        int v = __ldg(ei32 + 2 * threadIdx.x + 1);
        unsigned m = __ballot_sync(0xffffffffu, v == 0);
        if (threadIdx.x == 0) sh = (m == 0xffffffffu) ? 1 : 0;
    }
    __syncthreads();
    return sh;
}

__device__ __forceinline__ int load_idx(const void* ei, size_t pos, int is64) {
    if (is64) return (int)__ldg((const long long*)ei + pos);
    return __ldg((const int*)ei + pos);
}

// ---------------- CSR build ----------------
__global__ void __launch_bounds__(256) k_deg(const void* __restrict__ ei, int E) {
    int is64 = block_is64((const int*)ei);
    if (blockIdx.x < SCAN_BLOCKS && threadIdx.x == 0) g_scanstate[blockIdx.x] = 0u;
    int e = (blockIdx.x * 256 + threadIdx.x) * 2;
    if (e < E) atomicAdd(&g_cnt[load_idx(ei, (size_t)E + e, is64)], 1);
    if (e + 1 < E) atomicAdd(&g_cnt[load_idx(ei, (size_t)E + e + 1, is64)], 1);
}

// single-pass scan + apply (decoupled lookback; 196 blocks, all wave-1 resident).
// Produces rowptr/cursor/rdeg and resets g_cnt to 0 for the next call.
__global__ void __launch_bounds__(256) k_scanapply() {
    int b = blockIdx.x;
    int t = threadIdx.x;
    int lane = t & 31;
    int w = t >> 5;

    int i0 = b * SCAN_CHUNK + t * 2;
    int c0 = (i0 < NN) ? g_cnt[i0] : 0;
    int c1 = (i0 + 1 < NN) ? g_cnt[i0 + 1] : 0;
    int s = c0 + c1;

    // warp inclusive scan
    int incl = s;
#pragma unroll
    for (int off = 1; off < 32; off <<= 1) {
        int n = __shfl_up_sync(0xffffffffu, incl, off);
        if (lane >= off) incl += n;
    }
    __shared__ int wsum[8];
    __shared__ int sh_excl;
    if (lane == 31) wsum[w] = incl;
    __syncthreads();

    // publish aggregate (or inclusive for block 0)
    if (t == 0) {
        int tot = 0;
#pragma unroll
        for (int i = 0; i < 8; i++) tot += wsum[i];
        unsigned pub = ((b == 0) ? ST_INC : ST_AGG) | (unsigned)tot;
        atomicExch(&g_scanstate[b], pub);
    }

    // warp 0: lookback
    if (w == 0) {
        int excl = 0;
        if (b > 0) {
            int lb = b - 1;
            while (true) {
                int idx = lb - lane;
                unsigned v;
                if (idx < 0) {
                    v = ST_INC;  // value 0 terminator
                } else {
                    volatile unsigned* p = (volatile unsigned*)&g_scanstate[idx];
                    do { v = *p; } while (v == 0u);
                }
                unsigned st = v & 0xC0000000u;
                int val = (int)(v & ST_VAL);
                unsigned mInc = __ballot_sync(0xffffffffu, st == ST_INC);
                int li = __ffs(mInc) - 1;  // nearest inclusive predecessor
                int take = (mInc == 0u) ? 1 : (lane <= li);
                int contrib = take ? val : 0;
#pragma unroll
                for (int off = 16; off; off >>= 1)
                    contrib += __shfl_down_sync(0xffffffffu, contrib, off);
                contrib = __shfl_sync(0xffffffffu, contrib, 0);
                excl += contrib;
                if (mInc) break;
                lb -= 32;
            }
        }
        if (lane == 0) {
            sh_excl = excl;
            int tot = 0;
#pragma unroll
            for (int i = 0; i < 8; i++) tot += wsum[i];
            if (b > 0) atomicExch(&g_scanstate[b], ST_INC | (unsigned)(excl + tot));
            if (b == SCAN_BLOCKS - 1) g_rowptr[NN] = excl + tot;
        }
    }
    __syncthreads();

    int excl = sh_excl;
    int woff = 0;
#pragma unroll
    for (int i = 0; i < 8; i++)
        if (i < w) woff += wsum[i];
    int run = excl + woff + incl - s;  // exclusive prefix for i0

    if (i0 < NN) {
        g_rowptr[i0] = run;
        g_cursor[i0] = run;
        g_rdeg[i0] = 1.0f / (float)max(c0, 1);
        g_cnt[i0] = 0;  // reset for next call
        run += c0;
    }
    if (i0 + 1 < NN) {
        g_rowptr[i0 + 1] = run;
        g_cursor[i0 + 1] = run;
        g_rdeg[i0 + 1] = 1.0f / (float)max(c1, 1);
        g_cnt[i0 + 1] = 0;
    }
}

__global__ void __launch_bounds__(256) k_fill(const void* __restrict__ ei, int E) {
    int is64 = block_is64((const int*)ei);
    int e = (blockIdx.x * 256 + threadIdx.x) * 2;
    if (e < E) {
        int src = load_idx(ei, (size_t)e, is64);
        int dst = load_idx(ei, (size_t)E + e, is64);
        g_csr[atomicAdd(&g_cursor[dst], 1)] = src;
    }
    if (e + 1 < E) {
        int src = load_idx(ei, (size_t)e + 1, is64);
        int dst = load_idx(ei, (size_t)E + e + 1, is64);
        g_csr[atomicAdd(&g_cursor[dst], 1)] = src;
    }
}

// ---------------- aggregation: warp per dst node, 8 rows in flight ----------------
// 16 lanes cover one 256B row (float4 each); sub = which of 2 parallel edges.
// srcsel: 0 = external x, 1 = g_buf1, 2 = g_buf2
__global__ void __launch_bounds__(256) k_agg(const float* __restrict__ xin, int srcsel) {
    const float* h = (srcsel == 0) ? xin : (srcsel == 1) ? g_buf1 : g_buf2;
    int w = blockIdx.x * 8 + (threadIdx.x >> 5);
    if (w >= NN) return;
    int lane = threadIdx.x & 31;
    int sub = lane >> 4;
    int c = lane & 15;
    int beg = g_rowptr[w];
    int end = g_rowptr[w + 1];
    const float4* hp = (const float4*)h;

    float ax0 = 0.f, ay0 = 0.f, az0 = 0.f, aw0 = 0.f;   // chain A
    float ax1 = 0.f, ay1 = 0.f, az1 = 0.f, aw1 = 0.f;   // chain B
    int j = beg + sub;
    // 4 edges per sub per iteration -> 8 independent row loads per warp
    for (; j + 6 < end; j += 8) {
        int s0 = g_csr[j];
        int s1 = g_csr[j + 2];
        int s2 = g_csr[j + 4];
        int s3 = g_csr[j + 6];
        float4 v0 = __ldg(hp + s0 * 16 + c);
        float4 v1 = __ldg(hp + s1 * 16 + c);
        float4 v2 = __ldg(hp + s2 * 16 + c);
        float4 v3 = __ldg(hp + s3 * 16 + c);
        ax0 += v0.x; ay0 += v0.y; az0 += v0.z; aw0 += v0.w;
        ax1 += v1.x; ay1 += v1.y; az1 += v1.z; aw1 += v1.w;
        ax0 += v2.x; ay0 += v2.y; az0 += v2.z; aw0 += v2.w;
        ax1 += v3.x; ay1 += v3.y; az1 += v3.z; aw1 += v3.w;
    }
    for (; j < end; j += 2) {
        float4 v = __ldg(hp + g_csr[j] * 16 + c);
        ax0 += v.x; ay0 += v.y; az0 += v.z; aw0 += v.w;
    }
    float x = ax0 + ax1, y = ay0 + ay1, z = az0 + az1, ww = aw0 + aw1;
    x += __shfl_xor_sync(0xffffffffu, x, 16);
    y += __shfl_xor_sync(0xffffffffu, y, 16);
    z += __shfl_xor_sync(0xffffffffu, z, 16);
    ww += __shfl_xor_sync(0xffffffffu, ww, 16);
    if (sub == 0) {
        float rd = g_rdeg[w];
        float4 r;
        r.x = x * rd; r.y = y * rd; r.z = z * rd; r.w = ww * rd;
        ((float4*)g_mean)[w * 16 + c] = r;
    }
}

// ---------------- fused dual-GEMM: out = h@Ws + mean@Wn + b (opt relu) ----------------
// 64 nodes per block, 256 threads: thread = (node, quarter), 16 cols each = 8 f32x2 accs.
// Static shared only (33 KB): transposed feature tile (65-pad) + weight tile.
// fp32 packed FMA (fma.rn.f32x2) doubles fp32 MAC throughput on sm_103a.
template <bool RELU>
__global__ void __launch_bounds__(256) k_gemm(const float* __restrict__ xin,
                                              const float* __restrict__ Ws,
                                              const float* __restrict__ Wn,
                                              const float* __restrict__ bias,
                                              float* __restrict__ outp,
                                              int srcsel, int dstsel) {
    __shared__ float sh_t[64 * 65];   // [k][node], padded
    __shared__ float sw[64 * 64];     // [k][col]

    const float* hin = (srcsel == 0) ? xin : (srcsel == 1) ? g_buf1 : g_buf2;
    float* out = (dstsel == 0) ? outp : (dstsel == 1) ? g_buf1 : g_buf2;

    int t = threadIdx.x;
    int base = blockIdx.x * 64;

    unsigned long long acc[8];
#pragma unroll
    for (int i = 0; i < 8; i++) acc[i] = 0ull;

    int node = t >> 2;   // 0..63
    int q = t & 3;       // 0..3 (16 cols each)

    for (int p = 0; p < 2; p++) {
        const float* src = (p == 0) ? hin : g_mean;
        const float* W = (p == 0) ? Ws : Wn;
        if (p) __syncthreads();  // previous compute done before overwriting tiles

        // weights: 1024 float4s
#pragma unroll
        for (int i = 0; i < 4; i++) {
            int idx = t + i * 256;
            ((float4*)sw)[idx] = ((const float4*)W)[idx];
        }
        // feature tile: 64 rows x 64 cols, store transposed into sh_t[k*65+node]
#pragma unroll
        for (int i = 0; i < 4; i++) {
            int idx = t + i * 256;
            int row = idx >> 4;
            int c4 = idx & 15;
            float4 v;
            if (base + row < NN) {
                v = ((const float4*)(src + (size_t)(base + row) * 64))[c4];
            } else {
                v.x = v.y = v.z = v.w = 0.f;
            }
            int kc = c4 * 4;
            sh_t[(kc + 0) * 65 + row] = v.x;
            sh_t[(kc + 1) * 65 + row] = v.y;
            sh_t[(kc + 2) * 65 + row] = v.z;
            sh_t[(kc + 3) * 65 + row] = v.w;
        }
        __syncthreads();

#pragma unroll 8
        for (int k = 0; k < 64; k++) {
            float a = sh_t[k * 65 + node];
            unsigned long long a2;
            asm("mov.b64 %0, {%1, %1};" : "=l"(a2) : "f"(a));
            const ulonglong2* wr = (const ulonglong2*)(sw + k * 64 + q * 16);
#pragma unroll
            for (int i = 0; i < 4; i++) {
                ulonglong2 w = wr[i];
                asm("fma.rn.f32x2 %0, %1, %2, %0;" : "+l"(acc[2 * i]) : "l"(w.x), "l"(a2));
                asm("fma.rn.f32x2 %0, %1, %2, %0;" : "+l"(acc[2 * i + 1]) : "l"(w.y), "l"(a2));
            }
        }
    }

    int g = base + node;
    if (g < NN) {
        float* op = out + (size_t)g * 64 + q * 16;
        const float* bp = bias + q * 16;
#pragma unroll
        for (int i = 0; i < 4; i++) {
            float v0, v1, v2, v3;
            asm("mov.b64 {%0, %1}, %2;" : "=f"(v0), "=f"(v1) : "l"(acc[2 * i]));
            asm("mov.b64 {%0, %1}, %2;" : "=f"(v2), "=f"(v3) : "l"(acc[2 * i + 1]));
            v0 += __ldg(bp + 4 * i + 0);
            v1 += __ldg(bp + 4 * i + 1);
            v2 += __ldg(bp + 4 * i + 2);
            v3 += __ldg(bp + 4 * i + 3);
            if (RELU) {
                v0 = fmaxf(v0, 0.f); v1 = fmaxf(v1, 0.f);
                v2 = fmaxf(v2, 0.f); v3 = fmaxf(v3, 0.f);
            }
            float4 o;
            o.x = v0; o.y = v1; o.z = v2; o.w = v3;
            ((float4*)op)[i] = o;
        }
    }
}

// ---------------- launch: kernel launches ONLY (graph-capture safe) ----------------
extern "C" void kernel_launch(void* const* d_in, const int* in_sizes, int n_in,
                              void* d_out, int out_size) {
    const float* x = (const float*)d_in[0];
    const void* ei = d_in[1];
    const float* ws1 = (const float*)d_in[2];
    const float* wn1 = (const float*)d_in[3];
    const float* b1  = (const float*)d_in[4];
    const float* ws2 = (const float*)d_in[5];
    const float* wn2 = (const float*)d_in[6];
    const float* b2  = (const float*)d_in[7];
    const float* ws3 = (const float*)d_in[8];
    const float* wn3 = (const float*)d_in[9];
    const float* b3  = (const float*)d_in[10];
    float* out = (float*)d_out;

    int E = in_sizes[1] / 2;   // element count / 2, dtype-independent

    int eb2 = (E / 2 + 255) / 256;       // 2 edges per thread
    int aggBlocks = (NN + 7) / 8;        // warp per node
    int gemmBlocks = (NN + 63) / 64;     // 1563

    // CSR build: deg(0) -> scan+apply(1) -> fill(2); cnt re-zeroed inside scanapply
    k_deg<<<eb2, 256>>>(ei, E);
    k_scanapply<<<SCAN_BLOCKS, 256>>>();
    k_fill<<<eb2, 256>>>(ei, E);

    // layer 1: x -> g_buf1    (k_agg at launch index 3 -> profiled by ncu)
    k_agg<<<aggBlocks, 256>>>(x, 0);
    k_gemm<true><<<gemmBlocks, 256>>>(x, ws1, wn1, b1, out, 0, 1);
    // layer 2: g_buf1 -> g_buf2
    k_agg<<<aggBlocks, 256>>>(x, 1);
    k_gemm<true><<<gemmBlocks, 256>>>(x, ws2, wn2, b2, out, 1, 2);
    // layer 3: g_buf2 -> out
    k_agg<<<aggBlocks, 256>>>(x, 2);
    k_gemm<false><<<gemmBlocks, 256>>>(x, ws3, wn3, b3, out, 2, 0);
}

// round 8
// speedup vs baseline: 1.0013x; 1.0013x over previous
#include <cuda_runtime.h>
#include <cuda_bf16.h>

#define NN   100000
#define NPAD 100096
#define EMAX 1600000
#define D    64

#define SCAN_CHUNK  512
#define SCAN_BLOCKS ((NN + SCAN_CHUNK - 1) / SCAN_CHUNK)   // 196

#define ST_AGG (1u << 30)
#define ST_INC (2u << 30)
#define ST_VAL 0x00FFFFFFu

// ---------------- scratch (static device globals; no allocation) ----------------
__device__ float g_buf1[NPAD * D];
__device__ float g_buf2[NPAD * D];
__device__ float g_mean[NPAD * D];
__device__ int   g_csr[EMAX];
__device__ int   g_rowptr[NN + 1];
__device__ int   g_cnt[NN];        // zero-initialized; k_scanapply re-zeroes after use
__device__ int   g_cursor[NN];
__device__ float g_rdeg[NN];
__device__ unsigned g_scanstate[SCAN_BLOCKS];  // zeroed by k_deg each call

// ---------------- helpers ----------------
// int64 edge_index (little-endian, values < 2^31) has all-zero odd 32-bit words.
__device__ __forceinline__ int block_is64(const int* __restrict__ ei32) {
    __shared__ int sh;
    if (threadIdx.x < 32) {
        int v = __ldg(ei32 + 2 * threadIdx.x + 1);
        unsigned m = __ballot_sync(0xffffffffu, v == 0);
        if (threadIdx.x == 0) sh = (m == 0xffffffffu) ? 1 : 0;
    }
    __syncthreads();
    return sh;
}

__device__ __forceinline__ int load_idx(const void* ei, size_t pos, int is64) {
    if (is64) return (int)__ldg((const long long*)ei + pos);
    return __ldg((const int*)ei + pos);
}

// ---------------- CSR build ----------------
__global__ void __launch_bounds__(256) k_deg(const void* __restrict__ ei, int E) {
    int is64 = block_is64((const int*)ei);
    if (blockIdx.x < SCAN_BLOCKS && threadIdx.x == 0) g_scanstate[blockIdx.x] = 0u;
    int e = (blockIdx.x * 256 + threadIdx.x) * 2;
    if (e < E) atomicAdd(&g_cnt[load_idx(ei, (size_t)E + e, is64)], 1);
    if (e + 1 < E) atomicAdd(&g_cnt[load_idx(ei, (size_t)E + e + 1, is64)], 1);
}

// single-pass scan + apply (decoupled lookback; 196 blocks, all wave-1 resident).
// Produces rowptr/cursor/rdeg and resets g_cnt to 0 for the next call.
__global__ void __launch_bounds__(256) k_scanapply() {
    int b = blockIdx.x;
    int t = threadIdx.x;
    int lane = t & 31;
    int w = t >> 5;

    int i0 = b * SCAN_CHUNK + t * 2;
    int c0 = (i0 < NN) ? g_cnt[i0] : 0;
    int c1 = (i0 + 1 < NN) ? g_cnt[i0 + 1] : 0;
    int s = c0 + c1;

    // warp inclusive scan
    int incl = s;
#pragma unroll
    for (int off = 1; off < 32; off <<= 1) {
        int n = __shfl_up_sync(0xffffffffu, incl, off);
        if (lane >= off) incl += n;
    }
    __shared__ int wsum[8];
    __shared__ int sh_excl;
    if (lane == 31) wsum[w] = incl;
    __syncthreads();

    // publish aggregate (or inclusive for block 0)
    if (t == 0) {
        int tot = 0;
#pragma unroll
        for (int i = 0; i < 8; i++) tot += wsum[i];
        unsigned pub = ((b == 0) ? ST_INC : ST_AGG) | (unsigned)tot;
        atomicExch(&g_scanstate[b], pub);
    }

    // warp 0: lookback
    if (w == 0) {
        int excl = 0;
        if (b > 0) {
            int lb = b - 1;
            while (true) {
                int idx = lb - lane;
                unsigned v;
                if (idx < 0) {
                    v = ST_INC;  // value 0 terminator
                } else {
                    volatile unsigned* p = (volatile unsigned*)&g_scanstate[idx];
                    do { v = *p; } while (v == 0u);
                }
                unsigned st = v & 0xC0000000u;
                int val = (int)(v & ST_VAL);
                unsigned mInc = __ballot_sync(0xffffffffu, st == ST_INC);
                int li = __ffs(mInc) - 1;  // nearest inclusive predecessor
                int take = (mInc == 0u) ? 1 : (lane <= li);
                int contrib = take ? val : 0;
#pragma unroll
                for (int off = 16; off; off >>= 1)
                    contrib += __shfl_down_sync(0xffffffffu, contrib, off);
                contrib = __shfl_sync(0xffffffffu, contrib, 0);
                excl += contrib;
                if (mInc) break;
                lb -= 32;
            }
        }
        if (lane == 0) {
            sh_excl = excl;
            int tot = 0;
#pragma unroll
            for (int i = 0; i < 8; i++) tot += wsum[i];
            if (b > 0) atomicExch(&g_scanstate[b], ST_INC | (unsigned)(excl + tot));
            if (b == SCAN_BLOCKS - 1) g_rowptr[NN] = excl + tot;
        }
    }
    __syncthreads();

    int excl = sh_excl;
    int woff = 0;
#pragma unroll
    for (int i = 0; i < 8; i++)
        if (i < w) woff += wsum[i];
    int run = excl + woff + incl - s;  // exclusive prefix for i0

    if (i0 < NN) {
        g_rowptr[i0] = run;
        g_cursor[i0] = run;
        g_rdeg[i0] = 1.0f / (float)max(c0, 1);
        g_cnt[i0] = 0;  // reset for next call
        run += c0;
    }
    if (i0 + 1 < NN) {
        g_rowptr[i0 + 1] = run;
        g_cursor[i0 + 1] = run;
        g_rdeg[i0 + 1] = 1.0f / (float)max(c1, 1);
        g_cnt[i0 + 1] = 0;
    }
}

__global__ void __launch_bounds__(256) k_fill(const void* __restrict__ ei, int E) {
    int is64 = block_is64((const int*)ei);
    int e = (blockIdx.x * 256 + threadIdx.x) * 2;
    if (e < E) {
        int src = load_idx(ei, (size_t)e, is64);
        int dst = load_idx(ei, (size_t)E + e, is64);
        g_csr[atomicAdd(&g_cursor[dst], 1)] = src;
    }
    if (e + 1 < E) {
        int src = load_idx(ei, (size_t)e + 1, is64);
        int dst = load_idx(ei, (size_t)E + e + 1, is64);
        g_csr[atomicAdd(&g_cursor[dst], 1)] = src;
    }
}

// ---------------- aggregation: warp per dst node, 8 rows in flight ----------------
// 16 lanes cover one 256B row (float4 each); sub = which of 2 parallel edges.
// srcsel: 0 = external x, 1 = g_buf1, 2 = g_buf2
__global__ void __launch_bounds__(256) k_agg(const float* __restrict__ xin, int srcsel) {
    const float* h = (srcsel == 0) ? xin : (srcsel == 1) ? g_buf1 : g_buf2;
    int w = blockIdx.x * 8 + (threadIdx.x >> 5);
    if (w >= NN) return;
    int lane = threadIdx.x & 31;
    int sub = lane >> 4;
    int c = lane & 15;
    int beg = g_rowptr[w];
    int end = g_rowptr[w + 1];
    const float4* hp = (const float4*)h;

    float ax0 = 0.f, ay0 = 0.f, az0 = 0.f, aw0 = 0.f;   // chain A
    float ax1 = 0.f, ay1 = 0.f, az1 = 0.f, aw1 = 0.f;   // chain B
    int j = beg + sub;
    // 4 edges per sub per iteration -> 8 independent row loads per warp
    for (; j + 6 < end; j += 8) {
        int s0 = g_csr[j];
        int s1 = g_csr[j + 2];
        int s2 = g_csr[j + 4];
        int s3 = g_csr[j + 6];
        float4 v0 = __ldg(hp + s0 * 16 + c);
        float4 v1 = __ldg(hp + s1 * 16 + c);
        float4 v2 = __ldg(hp + s2 * 16 + c);
        float4 v3 = __ldg(hp + s3 * 16 + c);
        ax0 += v0.x; ay0 += v0.y; az0 += v0.z; aw0 += v0.w;
        ax1 += v1.x; ay1 += v1.y; az1 += v1.z; aw1 += v1.w;
        ax0 += v2.x; ay0 += v2.y; az0 += v2.z; aw0 += v2.w;
        ax1 += v3.x; ay1 += v3.y; az1 += v3.z; aw1 += v3.w;
    }
    for (; j < end; j += 2) {
        float4 v = __ldg(hp + g_csr[j] * 16 + c);
        ax0 += v.x; ay0 += v.y; az0 += v.z; aw0 += v.w;
    }
    float x = ax0 + ax1, y = ay0 + ay1, z = az0 + az1, ww = aw0 + aw1;
    x += __shfl_xor_sync(0xffffffffu, x, 16);
    y += __shfl_xor_sync(0xffffffffu, y, 16);
    z += __shfl_xor_sync(0xffffffffu, z, 16);
    ww += __shfl_xor_sync(0xffffffffu, ww, 16);
    if (sub == 0) {
        float rd = g_rdeg[w];
        float4 r;
        r.x = x * rd; r.y = y * rd; r.z = z * rd; r.w = ww * rd;
        ((float4*)g_mean)[w * 16 + c] = r;
    }
}

// ---------------- fused dual-GEMM: out = h@Ws + mean@Wn + b (opt relu) ----------------
// 64 nodes per block, 256 threads: thread = (node, quarter), 16 cols each = 8 f32x2 accs.
// Static shared only (33 KB): transposed feature tile (65-pad) + weight tile.
// fp32 packed FMA (fma.rn.f32x2) doubles fp32 MAC throughput on sm_103a.
template <bool RELU>
__global__ void __launch_bounds__(256) k_gemm(const float* __restrict__ xin,
                                              const float* __restrict__ Ws,
                                              const float* __restrict__ Wn,
                                              const float* __restrict__ bias,
                                              float* __restrict__ outp,
                                              int srcsel, int dstsel) {
    __shared__ float sh_t[64 * 65];   // [k][node], padded
    __shared__ float sw[64 * 64];     // [k][col]

    const float* hin = (srcsel == 0) ? xin : (srcsel == 1) ? g_buf1 : g_buf2;
    float* out = (dstsel == 0) ? outp : (dstsel == 1) ? g_buf1 : g_buf2;

    int t = threadIdx.x;
    int base = blockIdx.x * 64;

    unsigned long long acc[8];
#pragma unroll
    for (int i = 0; i < 8; i++) acc[i] = 0ull;

    int node = t >> 2;   // 0..63
    int q = t & 3;       // 0..3 (16 cols each)

    for (int p = 0; p < 2; p++) {
        const float* src = (p == 0) ? hin : g_mean;
        const float* W = (p == 0) ? Ws : Wn;
        if (p) __syncthreads();  // previous compute done before overwriting tiles

        // weights: 1024 float4s
#pragma unroll
        for (int i = 0; i < 4; i++) {
            int idx = t + i * 256;
            ((float4*)sw)[idx] = ((const float4*)W)[idx];
        }
        // feature tile: 64 rows x 64 cols, store transposed into sh_t[k*65+node]
#pragma unroll
        for (int i = 0; i < 4; i++) {
            int idx = t + i * 256;
            int row = idx >> 4;
            int c4 = idx & 15;
            float4 v;
            if (base + row < NN) {
                v = ((const float4*)(src + (size_t)(base + row) * 64))[c4];
            } else {
                v.x = v.y = v.z = v.w = 0.f;
            }
            int kc = c4 * 4;
            sh_t[(kc + 0) * 65 + row] = v.x;
            sh_t[(kc + 1) * 65 + row] = v.y;
            sh_t[(kc + 2) * 65 + row] = v.z;
            sh_t[(kc + 3) * 65 + row] = v.w;
        }
        __syncthreads();

#pragma unroll 8
        for (int k = 0; k < 64; k++) {
            float a = sh_t[k * 65 + node];
            unsigned long long a2;
            asm("mov.b64 %0, {%1, %1};" : "=l"(a2) : "f"(a));
            const ulonglong2* wr = (const ulonglong2*)(sw + k * 64 + q * 16);
#pragma unroll
            for (int i = 0; i < 4; i++) {
                ulonglong2 w = wr[i];
                asm("fma.rn.f32x2 %0, %1, %2, %0;" : "+l"(acc[2 * i]) : "l"(w.x), "l"(a2));
                asm("fma.rn.f32x2 %0, %1, %2, %0;" : "+l"(acc[2 * i + 1]) : "l"(w.y), "l"(a2));
            }
        }
    }

    int g = base + node;
    if (g < NN) {
        float* op = out + (size_t)g * 64 + q * 16;
        const float* bp = bias + q * 16;
#pragma unroll
        for (int i = 0; i < 4; i++) {
            float v0, v1, v2, v3;
            asm("mov.b64 {%0, %1}, %2;" : "=f"(v0), "=f"(v1) : "l"(acc[2 * i]));
            asm("mov.b64 {%0, %1}, %2;" : "=f"(v2), "=f"(v3) : "l"(acc[2 * i + 1]));
            v0 += __ldg(bp + 4 * i + 0);
            v1 += __ldg(bp + 4 * i + 1);
            v2 += __ldg(bp + 4 * i + 2);
            v3 += __ldg(bp + 4 * i + 3);
            if (RELU) {
                v0 = fmaxf(v0, 0.f); v1 = fmaxf(v1, 0.f);
                v2 = fmaxf(v2, 0.f); v3 = fmaxf(v3, 0.f);
            }
            float4 o;
            o.x = v0; o.y = v1; o.z = v2; o.w = v3;
            ((float4*)op)[i] = o;
        }
    }
}

// ---------------- launch: kernel launches ONLY (graph-capture safe) ----------------
extern "C" void kernel_launch(void* const* d_in, const int* in_sizes, int n_in,
                              void* d_out, int out_size) {
    const float* x = (const float*)d_in[0];
    const void* ei = d_in[1];
    const float* ws1 = (const float*)d_in[2];
    const float* wn1 = (const float*)d_in[3];
    const float* b1  = (const float*)d_in[4];
    const float* ws2 = (const float*)d_in[5];
    const float* wn2 = (const float*)d_in[6];
    const float* b2  = (const float*)d_in[7];
    const float* ws3 = (const float*)d_in[8];
    const float* wn3 = (const float*)d_in[9];
    const float* b3  = (const float*)d_in[10];
    float* out = (float*)d_out;

    int E = in_sizes[1] / 2;   // element count / 2, dtype-independent

    int eb2 = (E / 2 + 255) / 256;       // 2 edges per thread
    int aggBlocks = (NN + 7) / 8;        // warp per node
    int gemmBlocks = (NN + 63) / 64;     // 1563

    // CSR build: deg(0) -> scan+apply(1) -> fill(2); cnt re-zeroed inside scanapply
    k_deg<<<eb2, 256>>>(ei, E);
    k_scanapply<<<SCAN_BLOCKS, 256>>>();
    k_fill<<<eb2, 256>>>(ei, E);

    // layer 1: x -> g_buf1    (k_agg at launch index 3 -> profiled by ncu)
    k_agg<<<aggBlocks, 256>>>(x, 0);
    k_gemm<true><<<gemmBlocks, 256>>>(x, ws1, wn1, b1, out, 0, 1);
    // layer 2: g_buf1 -> g_buf2
    k_agg<<<aggBlocks, 256>>>(x, 1);
    k_gemm<true><<<gemmBlocks, 256>>>(x, ws2, wn2, b2, out, 1, 2);
    // layer 3: g_buf2 -> out
    k_agg<<<aggBlocks, 256>>>(x, 2);
    k_gemm<false><<<gemmBlocks, 256>>>(x, ws3, wn3, b3, out, 2, 0);
}

// round 9
// speedup vs baseline: 1.2806x; 1.2790x over previous
#include <cuda_runtime.h>
#include <cuda_bf16.h>

#define NN   100000
#define NPAD 100096
#define EMAX 1600000
#define D    64

#define SCAN_CHUNK  512
#define SCAN_BLOCKS ((NN + SCAN_CHUNK - 1) / SCAN_CHUNK)   // 196

#define ST_AGG (1u << 30)
#define ST_INC (2u << 30)
#define ST_VAL 0x00FFFFFFu

// ---------------- scratch (static device globals; no allocation) ----------------
__device__ float g_buf1[NPAD * D];
__device__ float g_buf2[NPAD * D];
__device__ float g_mean[NPAD * D];
__device__ int   g_csr[EMAX];
__device__ int   g_rowptr[NN + 1];
__device__ int   g_cnt[NN];        // zero-initialized; k_scanapply re-zeroes after use
__device__ int   g_cursor[NN];
__device__ float g_rdeg[NN];
__device__ unsigned g_scanstate[SCAN_BLOCKS];  // zeroed by k_deg each call

// ---------------- helpers ----------------
__device__ __forceinline__ int block_is64(const int* __restrict__ ei32) {
    __shared__ int sh;
    if (threadIdx.x < 32) {
        int v = __ldg(ei32 + 2 * threadIdx.x + 1);
        unsigned m = __ballot_sync(0xffffffffu, v == 0);
        if (threadIdx.x == 0) sh = (m == 0xffffffffu) ? 1 : 0;
    }
    __syncthreads();
    return sh;
}

__device__ __forceinline__ int load_idx(const void* ei, size_t pos, int is64) {
    if (is64) return (int)__ldg((const long long*)ei + pos);
    return __ldg((const int*)ei + pos);
}

// ---------------- CSR build ----------------
__global__ void __launch_bounds__(256) k_deg(const void* __restrict__ ei, int E) {
    int is64 = block_is64((const int*)ei);
    if (blockIdx.x < SCAN_BLOCKS && threadIdx.x == 0) g_scanstate[blockIdx.x] = 0u;
    int e = (blockIdx.x * 256 + threadIdx.x) * 2;
    if (e < E) atomicAdd(&g_cnt[load_idx(ei, (size_t)E + e, is64)], 1);
    if (e + 1 < E) atomicAdd(&g_cnt[load_idx(ei, (size_t)E + e + 1, is64)], 1);
}

// single-pass scan + apply (decoupled lookback). Resets g_cnt for next call.
__global__ void __launch_bounds__(256) k_scanapply() {
    int b = blockIdx.x;
    int t = threadIdx.x;
    int lane = t & 31;
    int w = t >> 5;

    int i0 = b * SCAN_CHUNK + t * 2;
    int c0 = (i0 < NN) ? g_cnt[i0] : 0;
    int c1 = (i0 + 1 < NN) ? g_cnt[i0 + 1] : 0;
    int s = c0 + c1;

    int incl = s;
#pragma unroll
    for (int off = 1; off < 32; off <<= 1) {
        int n = __shfl_up_sync(0xffffffffu, incl, off);
        if (lane >= off) incl += n;
    }
    __shared__ int wsum[8];
    __shared__ int sh_excl;
    if (lane == 31) wsum[w] = incl;
    __syncthreads();

    if (t == 0) {
        int tot = 0;
#pragma unroll
        for (int i = 0; i < 8; i++) tot += wsum[i];
        unsigned pub = ((b == 0) ? ST_INC : ST_AGG) | (unsigned)tot;
        atomicExch(&g_scanstate[b], pub);
    }

    if (w == 0) {
        int excl = 0;
        if (b > 0) {
            int lb = b - 1;
            while (true) {
                int idx = lb - lane;
                unsigned v;
                if (idx < 0) {
                    v = ST_INC;
                } else {
                    volatile unsigned* p = (volatile unsigned*)&g_scanstate[idx];
                    do { v = *p; } while (v == 0u);
                }
                unsigned st = v & 0xC0000000u;
                int val = (int)(v & ST_VAL);
                unsigned mInc = __ballot_sync(0xffffffffu, st == ST_INC);
                int li = __ffs(mInc) - 1;
                int take = (mInc == 0u) ? 1 : (lane <= li);
                int contrib = take ? val : 0;
#pragma unroll
                for (int off = 16; off; off >>= 1)
                    contrib += __shfl_down_sync(0xffffffffu, contrib, off);
                contrib = __shfl_sync(0xffffffffu, contrib, 0);
                excl += contrib;
                if (mInc) break;
                lb -= 32;
            }
        }
        if (lane == 0) {
            sh_excl = excl;
            int tot = 0;
#pragma unroll
            for (int i = 0; i < 8; i++) tot += wsum[i];
            if (b > 0) atomicExch(&g_scanstate[b], ST_INC | (unsigned)(excl + tot));
            if (b == SCAN_BLOCKS - 1) g_rowptr[NN] = excl + tot;
        }
    }
    __syncthreads();

    int excl = sh_excl;
    int woff = 0;
#pragma unroll
    for (int i = 0; i < 8; i++)
        if (i < w) woff += wsum[i];
    int run = excl + woff + incl - s;

    if (i0 < NN) {
        g_rowptr[i0] = run;
        g_cursor[i0] = run;
        g_rdeg[i0] = 1.0f / (float)max(c0, 1);
        g_cnt[i0] = 0;
        run += c0;
    }
    if (i0 + 1 < NN) {
        g_rowptr[i0 + 1] = run;
        g_cursor[i0 + 1] = run;
        g_rdeg[i0 + 1] = 1.0f / (float)max(c1, 1);
        g_cnt[i0 + 1] = 0;
    }
}

__global__ void __launch_bounds__(256) k_fill(const void* __restrict__ ei, int E) {
    int is64 = block_is64((const int*)ei);
    int e = (blockIdx.x * 256 + threadIdx.x) * 2;
    if (e < E) {
        int src = load_idx(ei, (size_t)e, is64);
        int dst = load_idx(ei, (size_t)E + e, is64);
        g_csr[atomicAdd(&g_cursor[dst], 1)] = src;
    }
    if (e + 1 < E) {
        int src = load_idx(ei, (size_t)e + 1, is64);
        int dst = load_idx(ei, (size_t)E + e + 1, is64);
        g_csr[atomicAdd(&g_cursor[dst], 1)] = src;
    }
}

// ---------------- aggregation: warp per dst node, 8 rows in flight ----------------
__global__ void __launch_bounds__(256) k_agg(const float* __restrict__ xin, int srcsel) {
    const float* h = (srcsel == 0) ? xin : (srcsel == 1) ? g_buf1 : g_buf2;
    int w = blockIdx.x * 8 + (threadIdx.x >> 5);
    if (w >= NN) return;
    int lane = threadIdx.x & 31;
    int sub = lane >> 4;
    int c = lane & 15;
    int beg = g_rowptr[w];
    int end = g_rowptr[w + 1];
    const float4* hp = (const float4*)h;

    float ax0 = 0.f, ay0 = 0.f, az0 = 0.f, aw0 = 0.f;
    float ax1 = 0.f, ay1 = 0.f, az1 = 0.f, aw1 = 0.f;
    int j = beg + sub;
    for (; j + 6 < end; j += 8) {
        int s0 = g_csr[j];
        int s1 = g_csr[j + 2];
        int s2 = g_csr[j + 4];
        int s3 = g_csr[j + 6];
        float4 v0 = __ldg(hp + s0 * 16 + c);
        float4 v1 = __ldg(hp + s1 * 16 + c);
        float4 v2 = __ldg(hp + s2 * 16 + c);
        float4 v3 = __ldg(hp + s3 * 16 + c);
        ax0 += v0.x; ay0 += v0.y; az0 += v0.z; aw0 += v0.w;
        ax1 += v1.x; ay1 += v1.y; az1 += v1.z; aw1 += v1.w;
        ax0 += v2.x; ay0 += v2.y; az0 += v2.z; aw0 += v2.w;
        ax1 += v3.x; ay1 += v3.y; az1 += v3.z; aw1 += v3.w;
    }
    for (; j < end; j += 2) {
        float4 v = __ldg(hp + g_csr[j] * 16 + c);
        ax0 += v.x; ay0 += v.y; az0 += v.z; aw0 += v.w;
    }
    float x = ax0 + ax1, y = ay0 + ay1, z = az0 + az1, ww = aw0 + aw1;
    x += __shfl_xor_sync(0xffffffffu, x, 16);
    y += __shfl_xor_sync(0xffffffffu, y, 16);
    z += __shfl_xor_sync(0xffffffffu, z, 16);
    ww += __shfl_xor_sync(0xffffffffu, ww, 16);
    if (sub == 0) {
        float rd = g_rdeg[w];
        float4 r;
        r.x = x * rd; r.y = y * rd; r.z = z * rd; r.w = ww * rd;
        ((float4*)g_mean)[w * 16 + c] = r;
    }
}

// ---------------- single GEMM: dst (=|+=) src@W (+bias) (opt relu) ----------------
// 128 nodes/block, 256 threads: thread = (node-pair, quarter) -> 2 nodes x 16 cols.
// Per k: 1 LDS.64 (a0,a1) + 4 LDS.128 (W, reused for both nodes) + 16 FFMA2.
// smem: tile [k][node] 64x128 (conflict-free, node-indexed) + W [k][col] = 48KB exactly.
// srcsel: 0=x 1=buf1 2=buf2 3=g_mean ; dstsel: 0=out 1=buf1 2=buf2
template <bool ADD, bool RELU>
__global__ void __launch_bounds__(256) k_gemm1(const float* __restrict__ xin,
                                               const float* __restrict__ W,
                                               const float* __restrict__ bias,
                                               float* __restrict__ outp,
                                               int srcsel, int dstsel) {
    __shared__ float sh_t[64 * 128];  // [k][node]
    __shared__ float sw[64 * 64];     // [k][col]

    const float* src = (srcsel == 0) ? xin : (srcsel == 1) ? g_buf1
                     : (srcsel == 2) ? g_buf2 : g_mean;
    float* out = (dstsel == 0) ? outp : (dstsel == 1) ? g_buf1 : g_buf2;

    int t = threadIdx.x;
    int base = blockIdx.x * 128;

    // stage W: 1024 float4s
#pragma unroll
    for (int i = 0; i < 4; i++) {
        int idx = t + i * 256;
        ((float4*)sw)[idx] = ((const float4*)W)[idx];
    }
    // stage feature tile transposed: 128 rows x 16 float4
#pragma unroll
    for (int i = 0; i < 8; i++) {
        int idx = t + i * 256;
        int row = idx >> 4;
        int c4 = idx & 15;
        float4 v;
        if (base + row < NN) {
            v = ((const float4*)(src + (size_t)(base + row) * 64))[c4];
        } else {
            v.x = v.y = v.z = v.w = 0.f;
        }
        int kc = c4 * 4;
        sh_t[(kc + 0) * 128 + row] = v.x;
        sh_t[(kc + 1) * 128 + row] = v.y;
        sh_t[(kc + 2) * 128 + row] = v.z;
        sh_t[(kc + 3) * 128 + row] = v.w;
    }
    __syncthreads();

    int p = t >> 2;      // node pair 0..63
    int q = t & 3;       // col quarter

    unsigned long long accA[8], accB[8];
#pragma unroll
    for (int i = 0; i < 8; i++) { accA[i] = 0ull; accB[i] = 0ull; }

#pragma unroll 4
    for (int k = 0; k < 64; k++) {
        float2 a = *(const float2*)(sh_t + k * 128 + 2 * p);
        unsigned long long a0, a1;
        asm("mov.b64 %0, {%1, %1};" : "=l"(a0) : "f"(a.x));
        asm("mov.b64 %0, {%1, %1};" : "=l"(a1) : "f"(a.y));
        const ulonglong2* wr = (const ulonglong2*)(sw + k * 64 + q * 16);
#pragma unroll
        for (int i = 0; i < 4; i++) {
            ulonglong2 wv = wr[i];
            asm("fma.rn.f32x2 %0, %1, %2, %0;" : "+l"(accA[2 * i])     : "l"(wv.x), "l"(a0));
            asm("fma.rn.f32x2 %0, %1, %2, %0;" : "+l"(accA[2 * i + 1]) : "l"(wv.y), "l"(a0));
            asm("fma.rn.f32x2 %0, %1, %2, %0;" : "+l"(accB[2 * i])     : "l"(wv.x), "l"(a1));
            asm("fma.rn.f32x2 %0, %1, %2, %0;" : "+l"(accB[2 * i + 1]) : "l"(wv.y), "l"(a1));
        }
    }

#pragma unroll 2
    for (int nn = 0; nn < 2; nn++) {
        int g = base + 2 * p + nn;
        if (g >= NN) break;
        unsigned long long* acc = nn ? accB : accA;
        float* op = out + (size_t)g * 64 + q * 16;
        const float* bp = bias + q * 16;
#pragma unroll
        for (int i = 0; i < 4; i++) {
            float v0, v1, v2, v3;
            asm("mov.b64 {%0, %1}, %2;" : "=f"(v0), "=f"(v1) : "l"(acc[2 * i]));
            asm("mov.b64 {%0, %1}, %2;" : "=f"(v2), "=f"(v3) : "l"(acc[2 * i + 1]));
            if (ADD) {
                float4 pv = ((const float4*)op)[i];
                v0 += pv.x; v1 += pv.y; v2 += pv.z; v3 += pv.w;
            } else {
                v0 += __ldg(bp + 4 * i + 0);
                v1 += __ldg(bp + 4 * i + 1);
                v2 += __ldg(bp + 4 * i + 2);
                v3 += __ldg(bp + 4 * i + 3);
            }
            if (RELU) {
                v0 = fmaxf(v0, 0.f); v1 = fmaxf(v1, 0.f);
                v2 = fmaxf(v2, 0.f); v3 = fmaxf(v3, 0.f);
            }
            float4 o;
            o.x = v0; o.y = v1; o.z = v2; o.w = v3;
            ((float4*)op)[i] = o;
        }
    }
}

// ---------------- launch: kernel launches ONLY (graph-capture safe) ----------------
extern "C" void kernel_launch(void* const* d_in, const int* in_sizes, int n_in,
                              void* d_out, int out_size) {
    const float* x = (const float*)d_in[0];
    const void* ei = d_in[1];
    const float* ws1 = (const float*)d_in[2];
    const float* wn1 = (const float*)d_in[3];
    const float* b1  = (const float*)d_in[4];
    const float* ws2 = (const float*)d_in[5];
    const float* wn2 = (const float*)d_in[6];
    const float* b2  = (const float*)d_in[7];
    const float* ws3 = (const float*)d_in[8];
    const float* wn3 = (const float*)d_in[9];
    const float* b3  = (const float*)d_in[10];
    float* out = (float*)d_out;

    int E = in_sizes[1] / 2;

    int eb2 = (E / 2 + 255) / 256;
    int aggBlocks = (NN + 7) / 8;
    int gemmBlocks = (NN + 127) / 128;   // 782

    // CSR build
    k_deg<<<eb2, 256>>>(ei, E);
    k_scanapply<<<SCAN_BLOCKS, 256>>>();
    k_fill<<<eb2, 256>>>(ei, E);

    // layer 1  (gemm_self at launch index 3 -> profiled)
    k_gemm1<false, false><<<gemmBlocks, 256>>>(x, ws1, b1, out, 0, 1);  // buf1 = x@Ws1+b1
    k_agg<<<aggBlocks, 256>>>(x, 0);                                    // mean(x)
    k_gemm1<true, true><<<gemmBlocks, 256>>>(x, wn1, b1, out, 3, 1);    // buf1 += mean@Wn1; relu

    // layer 2
    k_gemm1<false, false><<<gemmBlocks, 256>>>(x, ws2, b2, out, 1, 2);
    k_agg<<<aggBlocks, 256>>>(x, 1);
    k_gemm1<true, true><<<gemmBlocks, 256>>>(x, wn2, b2, out, 3, 2);

    // layer 3 (no relu)
    k_gemm1<false, false><<<gemmBlocks, 256>>>(x, ws3, b3, out, 2, 0);
    k_agg<<<aggBlocks, 256>>>(x, 2);
    k_gemm1<true, false><<<gemmBlocks, 256>>>(x, wn3, b3, out, 3, 0);
}

// round 10
// speedup vs baseline: 2.3086x; 1.8027x over previous
#include <cuda_runtime.h>
#include <cuda_bf16.h>

#define NN   100000
#define NPAD 100096
#define EMAX 1600000
#define D    64

#define SCAN_CHUNK  512
#define SCAN_BLOCKS ((NN + SCAN_CHUNK - 1) / SCAN_CHUNK)   // 196

#define ST_AGG (1u << 30)
#define ST_INC (2u << 30)
#define ST_VAL 0x00FFFFFFu

typedef unsigned long long ull;

// ---------------- scratch (static device globals; no allocation) ----------------
__device__ float g_buf1[NPAD * D];
__device__ float g_buf2[NPAD * D];
__device__ float g_mean[NPAD * D];
__device__ int   g_csr[EMAX];
__device__ int   g_rowptr[NN + 1];
__device__ int   g_cnt[NN];        // zero-initialized; k_scanapply re-zeroes after use
__device__ int   g_cursor[NN];
__device__ float g_rdeg[NN];
__device__ unsigned g_scanstate[SCAN_BLOCKS];  // zeroed by k_deg each call

// ---------------- helpers ----------------
__device__ __forceinline__ int block_is64(const int* __restrict__ ei32) {
    __shared__ int sh;
    if (threadIdx.x < 32) {
        int v = __ldg(ei32 + 2 * threadIdx.x + 1);
        unsigned m = __ballot_sync(0xffffffffu, v == 0);
        if (threadIdx.x == 0) sh = (m == 0xffffffffu) ? 1 : 0;
    }
    __syncthreads();
    return sh;
}

__device__ __forceinline__ int load_idx(const void* ei, size_t pos, int is64) {
    if (is64) return (int)__ldg((const long long*)ei + pos);
    return __ldg((const int*)ei + pos);
}

// ---------------- CSR build ----------------
__global__ void __launch_bounds__(256) k_deg(const void* __restrict__ ei, int E) {
    int is64 = block_is64((const int*)ei);
    if (blockIdx.x < SCAN_BLOCKS && threadIdx.x == 0) g_scanstate[blockIdx.x] = 0u;
    int e = (blockIdx.x * 256 + threadIdx.x) * 2;
    if (e < E) atomicAdd(&g_cnt[load_idx(ei, (size_t)E + e, is64)], 1);
    if (e + 1 < E) atomicAdd(&g_cnt[load_idx(ei, (size_t)E + e + 1, is64)], 1);
}

// single-pass scan + apply (decoupled lookback). Resets g_cnt for next call.
__global__ void __launch_bounds__(256) k_scanapply() {
    int b = blockIdx.x;
    int t = threadIdx.x;
    int lane = t & 31;
    int w = t >> 5;

    int i0 = b * SCAN_CHUNK + t * 2;
    int c0 = (i0 < NN) ? g_cnt[i0] : 0;
    int c1 = (i0 + 1 < NN) ? g_cnt[i0 + 1] : 0;
    int s = c0 + c1;

    int incl = s;
#pragma unroll
    for (int off = 1; off < 32; off <<= 1) {
        int n = __shfl_up_sync(0xffffffffu, incl, off);
        if (lane >= off) incl += n;
    }
    __shared__ int wsum[8];
    __shared__ int sh_excl;
    if (lane == 31) wsum[w] = incl;
    __syncthreads();

    if (t == 0) {
        int tot = 0;
#pragma unroll
        for (int i = 0; i < 8; i++) tot += wsum[i];
        unsigned pub = ((b == 0) ? ST_INC : ST_AGG) | (unsigned)tot;
        atomicExch(&g_scanstate[b], pub);
    }

    if (w == 0) {
        int excl = 0;
        if (b > 0) {
            int lb = b - 1;
            while (true) {
                int idx = lb - lane;
                unsigned v;
                if (idx < 0) {
                    v = ST_INC;
                } else {
                    volatile unsigned* p = (volatile unsigned*)&g_scanstate[idx];
                    do { v = *p; } while (v == 0u);
                }
                unsigned st = v & 0xC0000000u;
                int val = (int)(v & ST_VAL);
                unsigned mInc = __ballot_sync(0xffffffffu, st == ST_INC);
                int li = __ffs(mInc) - 1;
                int take = (mInc == 0u) ? 1 : (lane <= li);
                int contrib = take ? val : 0;
#pragma unroll
                for (int off = 16; off; off >>= 1)
                    contrib += __shfl_down_sync(0xffffffffu, contrib, off);
                contrib = __shfl_sync(0xffffffffu, contrib, 0);
                excl += contrib;
                if (mInc) break;
                lb -= 32;
            }
        }
        if (lane == 0) {
            sh_excl = excl;
            int tot = 0;
#pragma unroll
            for (int i = 0; i < 8; i++) tot += wsum[i];
            if (b > 0) atomicExch(&g_scanstate[b], ST_INC | (unsigned)(excl + tot));
            if (b == SCAN_BLOCKS - 1) g_rowptr[NN] = excl + tot;
        }
    }
    __syncthreads();

    int excl = sh_excl;
    int woff = 0;
#pragma unroll
    for (int i = 0; i < 8; i++)
        if (i < w) woff += wsum[i];
    int run = excl + woff + incl - s;

    if (i0 < NN) {
        g_rowptr[i0] = run;
        g_cursor[i0] = run;
        g_rdeg[i0] = 1.0f / (float)max(c0, 1);
        g_cnt[i0] = 0;
        run += c0;
    }
    if (i0 + 1 < NN) {
        g_rowptr[i0 + 1] = run;
        g_cursor[i0 + 1] = run;
        g_rdeg[i0 + 1] = 1.0f / (float)max(c1, 1);
        g_cnt[i0 + 1] = 0;
    }
}

__global__ void __launch_bounds__(256) k_fill(const void* __restrict__ ei, int E) {
    int is64 = block_is64((const int*)ei);
    int e = (blockIdx.x * 256 + threadIdx.x) * 2;
    if (e < E) {
        int src = load_idx(ei, (size_t)e, is64);
        int dst = load_idx(ei, (size_t)E + e, is64);
        g_csr[atomicAdd(&g_cursor[dst], 1)] = src;
    }
    if (e + 1 < E) {
        int src = load_idx(ei, (size_t)e + 1, is64);
        int dst = load_idx(ei, (size_t)E + e + 1, is64);
        g_csr[atomicAdd(&g_cursor[dst], 1)] = src;
    }
}

// ---------------- aggregation: warp per dst node, 8 rows in flight ----------------
__global__ void __launch_bounds__(256) k_agg(const float* __restrict__ xin, int srcsel) {
    const float* h = (srcsel == 0) ? xin : (srcsel == 1) ? g_buf1 : g_buf2;
    int w = blockIdx.x * 8 + (threadIdx.x >> 5);
    if (w >= NN) return;
    int lane = threadIdx.x & 31;
    int sub = lane >> 4;
    int c = lane & 15;
    int beg = g_rowptr[w];
    int end = g_rowptr[w + 1];
    const float4* hp = (const float4*)h;

    float ax0 = 0.f, ay0 = 0.f, az0 = 0.f, aw0 = 0.f;
    float ax1 = 0.f, ay1 = 0.f, az1 = 0.f, aw1 = 0.f;
    int j = beg + sub;
    for (; j + 6 < end; j += 8) {
        int s0 = g_csr[j];
        int s1 = g_csr[j + 2];
        int s2 = g_csr[j + 4];
        int s3 = g_csr[j + 6];
        float4 v0 = __ldg(hp + s0 * 16 + c);
        float4 v1 = __ldg(hp + s1 * 16 + c);
        float4 v2 = __ldg(hp + s2 * 16 + c);
        float4 v3 = __ldg(hp + s3 * 16 + c);
        ax0 += v0.x; ay0 += v0.y; az0 += v0.z; aw0 += v0.w;
        ax1 += v1.x; ay1 += v1.y; az1 += v1.z; aw1 += v1.w;
        ax0 += v2.x; ay0 += v2.y; az0 += v2.z; aw0 += v2.w;
        ax1 += v3.x; ay1 += v3.y; az1 += v3.z; aw1 += v3.w;
    }
    for (; j < end; j += 2) {
        float4 v = __ldg(hp + g_csr[j] * 16 + c);
        ax0 += v.x; ay0 += v.y; az0 += v.z; aw0 += v.w;
    }
    float x = ax0 + ax1, y = ay0 + ay1, z = az0 + az1, ww = aw0 + aw1;
    x += __shfl_xor_sync(0xffffffffu, x, 16);
    y += __shfl_xor_sync(0xffffffffu, y, 16);
    z += __shfl_xor_sync(0xffffffffu, z, 16);
    ww += __shfl_xor_sync(0xffffffffu, ww, 16);
    if (sub == 0) {
        float rd = g_rdeg[w];
        float4 r;
        r.x = x * rd; r.y = y * rd; r.z = z * rd; r.w = ww * rd;
        ((float4*)g_mean)[w * 16 + c] = r;
    }
}

// ---------------- GEMM: 128 nodes/block, 128 threads, 4 nodes x 16 cols/thread ----
// Tile [node][k] stride 65 -> conflict-free LDS.32 a-reads (bank = 4p+n).
// W quarter-swizzled rows of 80 floats (q*20) -> conflict-free LDS.128 reads.
// W staged in 2 slabs of 32 k-rows (10KB); total smem 43.5KB; >=4 blocks/SM.
// MODE: 0 = store srcA@WA + bias ; 1 = out += mean@WA (opt relu) ;
//       2 = fused: srcA@WA + mean@WB + bias (opt relu)
// srcsel: 0=x 1=buf1 2=buf2 ; dstsel: 0=out 1=buf1 2=buf2
#define PACK2(d, f) asm("mov.b64 %0, {%1, %1};" : "=l"(d) : "f"(f))
#define FMA2(d, a, b) asm("fma.rn.f32x2 %0, %1, %2, %0;" : "+l"(d) : "l"(a), "l"(b))

template <int MODE, bool RELU>
__global__ void __launch_bounds__(128, 4) k_gemm(const float* __restrict__ xin,
                                                 const float* __restrict__ WA,
                                                 const float* __restrict__ WB,
                                                 const float* __restrict__ bias,
                                                 float* __restrict__ outp,
                                                 int srcsel, int dstsel) {
    __shared__ float sh_a[128 * 65];   // 33280 B
    __shared__ float sh_w[32 * 80];    // 10240 B

    const float* srcA = (srcsel == 0) ? xin : (srcsel == 1) ? g_buf1 : g_buf2;
    float* out = (dstsel == 0) ? outp : (dstsel == 1) ? g_buf1 : g_buf2;

    int t = threadIdx.x;
    int base = blockIdx.x * 128;
    int p = t >> 2;   // node quad 0..31
    int q = t & 3;    // col quarter

    ull acc[4][8];
#pragma unroll
    for (int n = 0; n < 4; n++)
#pragma unroll
        for (int i = 0; i < 8; i++) acc[n][i] = 0ull;

    const int NPH = (MODE == 2) ? 2 : 1;
    for (int ph = 0; ph < NPH; ph++) {
        const float* src = (MODE == 1) ? g_mean : ((ph == 0) ? srcA : g_mean);
        const float* W = (ph == 0) ? WA : WB;
        if (ph) __syncthreads();   // phase-0 reads done before overwrite

        // stage feature tile [node][k], stride 65
#pragma unroll
        for (int it = 0; it < 16; it++) {
            int idx = t + it * 128;
            int row = idx >> 4;
            int c4 = idx & 15;
            float4 v = make_float4(0.f, 0.f, 0.f, 0.f);
            if (base + row < NN)
                v = ((const float4*)(src + (size_t)(base + row) * 64))[c4];
            float* d = sh_a + row * 65 + c4 * 4;
            d[0] = v.x; d[1] = v.y; d[2] = v.z; d[3] = v.w;
        }

        for (int kb = 0; kb < 64; kb += 32) {
            if (kb) __syncthreads();  // previous slab reads done
            // stage W slab: 32 rows, quarter-swizzled (q*20)
#pragma unroll
            for (int it = 0; it < 4; it++) {
                int idx = t + it * 128;
                int r = idx >> 4;
                int c4 = idx & 15;
                float4 v = ((const float4*)(W + (size_t)(kb + r) * 64))[c4];
                *(float4*)(sh_w + r * 80 + (c4 >> 2) * 20 + (c4 & 3) * 4) = v;
            }
            __syncthreads();

#pragma unroll 4
            for (int r = 0; r < 32; r++) {
                int k = kb + r;
                float a0 = sh_a[(4 * p + 0) * 65 + k];
                float a1 = sh_a[(4 * p + 1) * 65 + k];
                float a2 = sh_a[(4 * p + 2) * 65 + k];
                float a3 = sh_a[(4 * p + 3) * 65 + k];
                ull pa0, pa1, pa2, pa3;
                PACK2(pa0, a0); PACK2(pa1, a1); PACK2(pa2, a2); PACK2(pa3, a3);
                const ulonglong2* wr = (const ulonglong2*)(sh_w + r * 80 + q * 20);
#pragma unroll
                for (int i = 0; i < 4; i++) {
                    ulonglong2 wv = wr[i];
                    FMA2(acc[0][2 * i], wv.x, pa0); FMA2(acc[0][2 * i + 1], wv.y, pa0);
                    FMA2(acc[1][2 * i], wv.x, pa1); FMA2(acc[1][2 * i + 1], wv.y, pa1);
                    FMA2(acc[2][2 * i], wv.x, pa2); FMA2(acc[2][2 * i + 1], wv.y, pa2);
                    FMA2(acc[3][2 * i], wv.x, pa3); FMA2(acc[3][2 * i + 1], wv.y, pa3);
                }
            }
        }
    }

    // epilogue
#pragma unroll
    for (int n = 0; n < 4; n++) {
        int g = base + 4 * p + n;
        if (g < NN) {
            float* op = out + (size_t)g * 64 + q * 16;
            const float* bp = bias + q * 16;
#pragma unroll
            for (int i = 0; i < 4; i++) {
                float v0, v1, v2, v3;
                asm("mov.b64 {%0, %1}, %2;" : "=f"(v0), "=f"(v1) : "l"(acc[n][2 * i]));
                asm("mov.b64 {%0, %1}, %2;" : "=f"(v2), "=f"(v3) : "l"(acc[n][2 * i + 1]));
                if (MODE == 1) {
                    float4 pv = ((const float4*)op)[i];
                    v0 += pv.x; v1 += pv.y; v2 += pv.z; v3 += pv.w;
                } else {
                    v0 += __ldg(bp + 4 * i + 0);
                    v1 += __ldg(bp + 4 * i + 1);
                    v2 += __ldg(bp + 4 * i + 2);
                    v3 += __ldg(bp + 4 * i + 3);
                }
                if (RELU) {
                    v0 = fmaxf(v0, 0.f); v1 = fmaxf(v1, 0.f);
                    v2 = fmaxf(v2, 0.f); v3 = fmaxf(v3, 0.f);
                }
                float4 o;
                o.x = v0; o.y = v1; o.z = v2; o.w = v3;
                ((float4*)op)[i] = o;
            }
        }
    }
}

// ---------------- launch: kernel launches ONLY (graph-capture safe) ----------------
extern "C" void kernel_launch(void* const* d_in, const int* in_sizes, int n_in,
                              void* d_out, int out_size) {
    const float* x = (const float*)d_in[0];
    const void* ei = d_in[1];
    const float* ws1 = (const float*)d_in[2];
    const float* wn1 = (const float*)d_in[3];
    const float* b1  = (const float*)d_in[4];
    const float* ws2 = (const float*)d_in[5];
    const float* wn2 = (const float*)d_in[6];
    const float* b2  = (const float*)d_in[7];
    const float* ws3 = (const float*)d_in[8];
    const float* wn3 = (const float*)d_in[9];
    const float* b3  = (const float*)d_in[10];
    float* out = (float*)d_out;

    int E = in_sizes[1] / 2;

    int eb2 = (E / 2 + 255) / 256;
    int aggBlocks = (NN + 7) / 8;
    int gemmBlocks = (NN + 127) / 128;   // 782

    // CSR build
    k_deg<<<eb2, 256>>>(ei, E);
    k_scanapply<<<SCAN_BLOCKS, 256>>>();
    k_fill<<<eb2, 256>>>(ei, E);

    // layer 1 (split so the new GEMM is the profiled launch, index 3)
    k_gemm<0, false><<<gemmBlocks, 128>>>(x, ws1, ws1, b1, out, 0, 1);  // buf1 = x@Ws1+b1
    k_agg<<<aggBlocks, 256>>>(x, 0);                                    // mean(x)
    k_gemm<1, true><<<gemmBlocks, 128>>>(x, wn1, wn1, b1, out, 0, 1);   // buf1 += mean@Wn1; relu

    // layer 2 (fused dual)
    k_agg<<<aggBlocks, 256>>>(x, 1);                                    // mean(buf1)
    k_gemm<2, true><<<gemmBlocks, 128>>>(x, ws2, wn2, b2, out, 1, 2);   // buf2 = buf1@Ws2+mean@Wn2+b2; relu

    // layer 3 (fused dual, no relu)
    k_agg<<<aggBlocks, 256>>>(x, 2);                                    // mean(buf2)
    k_gemm<2, false><<<gemmBlocks, 128>>>(x, ws3, wn3, b3, out, 2, 0);  // out = buf2@Ws3+mean@Wn3+b3
}

// round 12
// speedup vs baseline: 2.6296x; 1.1390x over previous
#include <cuda_runtime.h>
#include <cuda_bf16.h>

#define NN   100000
#define NPAD 100096
#define EMAX 1600000
#define D    64

#define SCAN_CHUNK  512
#define SCAN_BLOCKS ((NN + SCAN_CHUNK - 1) / SCAN_CHUNK)   // 196

#define ST_AGG (1u << 30)
#define ST_INC (2u << 30)
#define ST_VAL 0x00FFFFFFu

typedef unsigned long long ull;

// ---------------- scratch (static device globals; no allocation) ----------------
__device__ float g_buf1[NPAD * D];
__device__ float g_buf2[NPAD * D];
__device__ float g_mean[NPAD * D];
__device__ int   g_csr[EMAX];
__device__ int   g_rowptr[NN + 1];
__device__ int   g_cnt[NN];        // zero-initialized; k_scanapply re-zeroes after use
__device__ int   g_cursor[NN];
__device__ float g_rdeg[NN];
__device__ unsigned g_scanstate[SCAN_BLOCKS];  // zeroed by k_deg each call

// ---------------- helpers ----------------
__device__ __forceinline__ int block_is64(const int* __restrict__ ei32) {
    __shared__ int sh;
    if (threadIdx.x < 32) {
        int v = __ldg(ei32 + 2 * threadIdx.x + 1);
        unsigned m = __ballot_sync(0xffffffffu, v == 0);
        if (threadIdx.x == 0) sh = (m == 0xffffffffu) ? 1 : 0;
    }
    __syncthreads();
    return sh;
}

__device__ __forceinline__ int load_idx(const void* ei, size_t pos, int is64) {
    if (is64) return (int)__ldg((const long long*)ei + pos);
    return __ldg((const int*)ei + pos);
}

// ---------------- CSR build ----------------
__global__ void __launch_bounds__(256) k_deg(const void* __restrict__ ei, int E) {
    int is64 = block_is64((const int*)ei);
    if (blockIdx.x < SCAN_BLOCKS && threadIdx.x == 0) g_scanstate[blockIdx.x] = 0u;
    int e = (blockIdx.x * 256 + threadIdx.x) * 2;
    if (e < E) atomicAdd(&g_cnt[load_idx(ei, (size_t)E + e, is64)], 1);
    if (e + 1 < E) atomicAdd(&g_cnt[load_idx(ei, (size_t)E + e + 1, is64)], 1);
}

// single-pass scan + apply (decoupled lookback). Resets g_cnt for next call.
__global__ void __launch_bounds__(256) k_scanapply() {
    int b = blockIdx.x;
    int t = threadIdx.x;
    int lane = t & 31;
    int w = t >> 5;

    int i0 = b * SCAN_CHUNK + t * 2;
    int c0 = (i0 < NN) ? g_cnt[i0] : 0;
    int c1 = (i0 + 1 < NN) ? g_cnt[i0 + 1] : 0;
    int s = c0 + c1;

    int incl = s;
#pragma unroll
    for (int off = 1; off < 32; off <<= 1) {
        int n = __shfl_up_sync(0xffffffffu, incl, off);
        if (lane >= off) incl += n;
    }
    __shared__ int wsum[8];
    __shared__ int sh_excl;
    if (lane == 31) wsum[w] = incl;
    __syncthreads();

    if (t == 0) {
        int tot = 0;
#pragma unroll
        for (int i = 0; i < 8; i++) tot += wsum[i];
        unsigned pub = ((b == 0) ? ST_INC : ST_AGG) | (unsigned)tot;
        atomicExch(&g_scanstate[b], pub);
    }

    if (w == 0) {
        int excl = 0;
        if (b > 0) {
            int lb = b - 1;
            while (true) {
                int idx = lb - lane;
                unsigned v;
                if (idx < 0) {
                    v = ST_INC;
                } else {
                    volatile unsigned* p = (volatile unsigned*)&g_scanstate[idx];
                    do { v = *p; } while (v == 0u);
                }
                unsigned st = v & 0xC0000000u;
                int val = (int)(v & ST_VAL);
                unsigned mInc = __ballot_sync(0xffffffffu, st == ST_INC);
                int li = __ffs(mInc) - 1;
                int take = (mInc == 0u) ? 1 : (lane <= li);
                int contrib = take ? val : 0;
#pragma unroll
                for (int off = 16; off; off >>= 1)
                    contrib += __shfl_down_sync(0xffffffffu, contrib, off);
                contrib = __shfl_sync(0xffffffffu, contrib, 0);
                excl += contrib;
                if (mInc) break;
                lb -= 32;
            }
        }
        if (lane == 0) {
            sh_excl = excl;
            int tot = 0;
#pragma unroll
            for (int i = 0; i < 8; i++) tot += wsum[i];
            if (b > 0) atomicExch(&g_scanstate[b], ST_INC | (unsigned)(excl + tot));
            if (b == SCAN_BLOCKS - 1) g_rowptr[NN] = excl + tot;
        }
    }
    __syncthreads();

    int excl = sh_excl;
    int woff = 0;
#pragma unroll
    for (int i = 0; i < 8; i++)
        if (i < w) woff += wsum[i];
    int run = excl + woff + incl - s;

    if (i0 < NN) {
        g_rowptr[i0] = run;
        g_cursor[i0] = run;
        g_rdeg[i0] = 1.0f / (float)max(c0, 1);
        g_cnt[i0] = 0;
        run += c0;
    }
    if (i0 + 1 < NN) {
        g_rowptr[i0 + 1] = run;
        g_cursor[i0 + 1] = run;
        g_rdeg[i0 + 1] = 1.0f / (float)max(c1, 1);
        g_cnt[i0 + 1] = 0;
    }
}

__global__ void __launch_bounds__(256) k_fill(const void* __restrict__ ei, int E) {
    int is64 = block_is64((const int*)ei);
    int e = (blockIdx.x * 256 + threadIdx.x) * 2;
    if (e < E) {
        int src = load_idx(ei, (size_t)e, is64);
        int dst = load_idx(ei, (size_t)E + e, is64);
        g_csr[atomicAdd(&g_cursor[dst], 1)] = src;
    }
    if (e + 1 < E) {
        int src = load_idx(ei, (size_t)e + 1, is64);
        int dst = load_idx(ei, (size_t)E + e + 1, is64);
        g_csr[atomicAdd(&g_cursor[dst], 1)] = src;
    }
}

// ---------------- aggregation: warp per dst node, 16 rows in flight ----------------
__global__ void __launch_bounds__(256) k_agg(const float* __restrict__ xin, int srcsel) {
    const float* h = (srcsel == 0) ? xin : (srcsel == 1) ? g_buf1 : g_buf2;
    int w = blockIdx.x * 8 + (threadIdx.x >> 5);
    if (w >= NN) return;
    int lane = threadIdx.x & 31;
    int sub = lane >> 4;
    int c = lane & 15;
    int beg = g_rowptr[w];
    int end = g_rowptr[w + 1];
    const float4* hp = (const float4*)h;

    float ax0 = 0.f, ay0 = 0.f, az0 = 0.f, aw0 = 0.f;
    float ax1 = 0.f, ay1 = 0.f, az1 = 0.f, aw1 = 0.f;
    int j = beg + sub;
    // 8 edges per sub per iteration -> 16 independent row loads per warp
    for (; j + 14 < end; j += 16) {
        int s0 = g_csr[j];
        int s1 = g_csr[j + 2];
        int s2 = g_csr[j + 4];
        int s3 = g_csr[j + 6];
        int s4 = g_csr[j + 8];
        int s5 = g_csr[j + 10];
        int s6 = g_csr[j + 12];
        int s7 = g_csr[j + 14];
        float4 v0 = __ldg(hp + s0 * 16 + c);
        float4 v1 = __ldg(hp + s1 * 16 + c);
        float4 v2 = __ldg(hp + s2 * 16 + c);
        float4 v3 = __ldg(hp + s3 * 16 + c);
        float4 v4 = __ldg(hp + s4 * 16 + c);
        float4 v5 = __ldg(hp + s5 * 16 + c);
        float4 v6 = __ldg(hp + s6 * 16 + c);
        float4 v7 = __ldg(hp + s7 * 16 + c);
        ax0 += v0.x; ay0 += v0.y; az0 += v0.z; aw0 += v0.w;
        ax1 += v1.x; ay1 += v1.y; az1 += v1.z; aw1 += v1.w;
        ax0 += v2.x; ay0 += v2.y; az0 += v2.z; aw0 += v2.w;
        ax1 += v3.x; ay1 += v3.y; az1 += v3.z; aw1 += v3.w;
        ax0 += v4.x; ay0 += v4.y; az0 += v4.z; aw0 += v4.w;
        ax1 += v5.x; ay1 += v5.y; az1 += v5.z; aw1 += v5.w;
        ax0 += v6.x; ay0 += v6.y; az0 += v6.z; aw0 += v6.w;
        ax1 += v7.x; ay1 += v7.y; az1 += v7.z; aw1 += v7.w;
    }
    for (; j < end; j += 2) {
        float4 v = __ldg(hp + g_csr[j] * 16 + c);
        ax0 += v.x; ay0 += v.y; az0 += v.z; aw0 += v.w;
    }
    float x = ax0 + ax1, y = ay0 + ay1, z = az0 + az1, ww = aw0 + aw1;
    x += __shfl_xor_sync(0xffffffffu, x, 16);
    y += __shfl_xor_sync(0xffffffffu, y, 16);
    z += __shfl_xor_sync(0xffffffffu, z, 16);
    ww += __shfl_xor_sync(0xffffffffu, ww, 16);
    if (sub == 0) {
        float rd = g_rdeg[w];
        float4 r;
        r.x = x * rd; r.y = y * rd; r.z = z * rd; r.w = ww * rd;
        ((float4*)g_mean)[w * 16 + c] = r;
    }
}

// ---------------- fused dual-GEMM: dst = srcA@WA + mean@WB + bias (opt relu) -------
// 128 nodes/block, 128 threads, 4 nodes x 16 cols/thread.
// Tile [node][k] stride 65 -> conflict-free LDS.32 a-reads; W quarter-swizzled
// rows (80 floats) -> conflict-free LDS.128; W staged in 2 slabs of 32 rows.
// a-values for k+1 prefetched during k's FMA burst to hide the 29-cyc LDS latency.
// srcsel: 0=x 1=buf1 2=buf2 ; dstsel: 0=out 1=buf1 2=buf2
#define PACK2(d, f) asm("mov.b64 %0, {%1, %1};" : "=l"(d) : "f"(f))
#define FMA2(d, a, b) asm("fma.rn.f32x2 %0, %1, %2, %0;" : "+l"(d) : "l"(a), "l"(b))

template <bool RELU>
__global__ void __launch_bounds__(128, 4) k_gemm(const float* __restrict__ xin,
                                                 const float* __restrict__ WA,
                                                 const float* __restrict__ WB,
                                                 const float* __restrict__ bias,
                                                 float* __restrict__ outp,
                                                 int srcsel, int dstsel) {
    __shared__ float sh_a[128 * 65];   // 33280 B
    __shared__ float sh_w[32 * 80];    // 10240 B

    const float* srcA = (srcsel == 0) ? xin : (srcsel == 1) ? g_buf1 : g_buf2;
    float* out = (dstsel == 0) ? outp : (dstsel == 1) ? g_buf1 : g_buf2;

    int t = threadIdx.x;
    int base = blockIdx.x * 128;
    int p = t >> 2;   // node quad 0..31
    int q = t & 3;    // col quarter

    ull acc[4][8];
#pragma unroll
    for (int n = 0; n < 4; n++)
#pragma unroll
        for (int i = 0; i < 8; i++) acc[n][i] = 0ull;

    for (int ph = 0; ph < 2; ph++) {
        const float* src = (ph == 0) ? srcA : g_mean;
        const float* W = (ph == 0) ? WA : WB;
        if (ph) __syncthreads();   // phase-0 reads done before overwrite

        // stage feature tile [node][k], stride 65
#pragma unroll
        for (int it = 0; it < 16; it++) {
            int idx = t + it * 128;
            int row = idx >> 4;
            int c4 = idx & 15;
            float4 v = make_float4(0.f, 0.f, 0.f, 0.f);
            if (base + row < NN)
                v = ((const float4*)(src + (size_t)(base + row) * 64))[c4];
            float* d = sh_a + row * 65 + c4 * 4;
            d[0] = v.x; d[1] = v.y; d[2] = v.z; d[3] = v.w;
        }

        for (int kb = 0; kb < 64; kb += 32) {
            if (kb) __syncthreads();  // previous slab reads done
            // stage W slab: 32 rows, quarter-swizzled (q*20)
#pragma unroll
            for (int it = 0; it < 4; it++) {
                int idx = t + it * 128;
                int r = idx >> 4;
                int c4 = idx & 15;
                float4 v = ((const float4*)(W + (size_t)(kb + r) * 64))[c4];
                *(float4*)(sh_w + r * 80 + (c4 >> 2) * 20 + (c4 & 3) * 4) = v;
            }
            __syncthreads();

            // a-prefetch pipeline
            float an0 = sh_a[(4 * p + 0) * 65 + kb];
            float an1 = sh_a[(4 * p + 1) * 65 + kb];
            float an2 = sh_a[(4 * p + 2) * 65 + kb];
            float an3 = sh_a[(4 * p + 3) * 65 + kb];
#pragma unroll 8
            for (int r = 0; r < 32; r++) {
                ull pa0, pa1, pa2, pa3;
                PACK2(pa0, an0); PACK2(pa1, an1); PACK2(pa2, an2); PACK2(pa3, an3);
                if (r < 31) {
                    int k = kb + r + 1;
                    an0 = sh_a[(4 * p + 0) * 65 + k];
                    an1 = sh_a[(4 * p + 1) * 65 + k];
                    an2 = sh_a[(4 * p + 2) * 65 + k];
                    an3 = sh_a[(4 * p + 3) * 65 + k];
                }
                const ulonglong2* wr = (const ulonglong2*)(sh_w + r * 80 + q * 20);
#pragma unroll
                for (int i = 0; i < 4; i++) {
                    ulonglong2 wv = wr[i];
                    FMA2(acc[0][2 * i], wv.x, pa0); FMA2(acc[0][2 * i + 1], wv.y, pa0);
                    FMA2(acc[1][2 * i], wv.x, pa1); FMA2(acc[1][2 * i + 1], wv.y, pa1);
                    FMA2(acc[2][2 * i], wv.x, pa2); FMA2(acc[2][2 * i + 1], wv.y, pa2);
                    FMA2(acc[3][2 * i], wv.x, pa3); FMA2(acc[3][2 * i + 1], wv.y, pa3);
                }
            }
        }
    }

    // epilogue: + bias (opt relu), store
#pragma unroll
    for (int n = 0; n < 4; n++) {
        int g = base + 4 * p + n;
        if (g < NN) {
            float* op = out + (size_t)g * 64 + q * 16;
            const float* bp = bias + q * 16;
#pragma unroll
            for (int i = 0; i < 4; i++) {
                float v0, v1, v2, v3;
                asm("mov.b64 {%0, %1}, %2;" : "=f"(v0), "=f"(v1) : "l"(acc[n][2 * i]));
                asm("mov.b64 {%0, %1}, %2;" : "=f"(v2), "=f"(v3) : "l"(acc[n][2 * i + 1]));
                v0 += __ldg(bp + 4 * i + 0);
                v1 += __ldg(bp + 4 * i + 1);
                v2 += __ldg(bp + 4 * i + 2);
                v3 += __ldg(bp + 4 * i + 3);
                if (RELU) {
                    v0 = fmaxf(v0, 0.f); v1 = fmaxf(v1, 0.f);
                    v2 = fmaxf(v2, 0.f); v3 = fmaxf(v3, 0.f);
                }
                float4 o;
                o.x = v0; o.y = v1; o.z = v2; o.w = v3;
                ((float4*)op)[i] = o;
            }
        }
    }
}

// ---------------- launch: kernel launches ONLY (graph-capture safe) ----------------
extern "C" void kernel_launch(void* const* d_in, const int* in_sizes, int n_in,
                              void* d_out, int out_size) {
    const float* x = (const float*)d_in[0];
    const void* ei = d_in[1];
    const float* ws1 = (const float*)d_in[2];
    const float* wn1 = (const float*)d_in[3];
    const float* b1  = (const float*)d_in[4];
    const float* ws2 = (const float*)d_in[5];
    const float* wn2 = (const float*)d_in[6];
    const float* b2  = (const float*)d_in[7];
    const float* ws3 = (const float*)d_in[8];
    const float* wn3 = (const float*)d_in[9];
    const float* b3  = (const float*)d_in[10];
    float* out = (float*)d_out;

    int E = in_sizes[1] / 2;

    int eb2 = (E / 2 + 255) / 256;
    int aggBlocks = (NN + 7) / 8;
    int gemmBlocks = (NN + 127) / 128;   // 782

    // CSR build
    k_deg<<<eb2, 256>>>(ei, E);
    k_scanapply<<<SCAN_BLOCKS, 256>>>();
    k_fill<<<eb2, 256>>>(ei, E);

    // layer 1: mean(x) first, then fully fused dual-GEMM (agg at profiled index 3)
    k_agg<<<aggBlocks, 256>>>(x, 0);                                    // mean(x)
    k_gemm<true><<<gemmBlocks, 128>>>(x, ws1, wn1, b1, out, 0, 1);      // buf1 = x@Ws1+mean@Wn1+b1; relu

    // layer 2
    k_agg<<<aggBlocks, 256>>>(x, 1);                                    // mean(buf1)
    k_gemm<true><<<gemmBlocks, 128>>>(x, ws2, wn2, b2, out, 1, 2);      // buf2 = ...; relu

    // layer 3 (no relu)
    k_agg<<<aggBlocks, 256>>>(x, 2);                                    // mean(buf2)
    k_gemm<false><<<gemmBlocks, 128>>>(x, ws3, wn3, b3, out, 2, 0);     // out = ...
}